// round 15
// baseline (speedup 1.0000x reference)
#include <cuda_runtime.h>
#include <cuda_fp16.h>
#include <cstdint>

// ---------------- problem constants ----------------
#define HID   4096
#define NEXP  4
#define RNK   8
#define MAXN  16384

// ---------------- GEMM tiling (fp16 operands) ----------------
#define BM 128
#define BN 256
#define BK 64
#define NCHUNK (HID / BK)             // 64
#define ROWB   144
#define A_ST   (BM * ROWB)            // 18432
#define B_ST   (BN * ROWB)            // 36864
#define STAGE_BYTES (A_ST + B_ST)     // 55296
#define STAGES 3
#define DYN_SMEM (STAGES * STAGE_BYTES)   // 165888
#define NROUND ((NCHUNK + 2) / 3)     // 22

// ---------------- gate tiling ----------------
#define TOKB 4                        // tokens per gate block
#define GATE_SMEM (TOKB * HID * 4)    // 64 KB x-row cache

// scratch (allocation-free rule: __device__ globals live in bss)
__device__ float   g_zs[MAXN * RNK];
__device__ int     g_top1[MAXN];
__device__ __half  g_xh[(size_t)MAXN * HID];   // fp16 x   (128 MB)
__device__ __half  g_wh[(size_t)HID * HID];    // fp16 W   (32 MB)

// ---------------- PTX helpers ----------------
__device__ __forceinline__ uint32_t smem_u32(const void* p) {
    uint32_t a;
    asm("{ .reg .u64 t; cvta.to.shared.u64 t, %1; cvt.u32.u64 %0, t; }"
        : "=r"(a) : "l"(p));
    return a;
}
__device__ __forceinline__ void cp_async16(uint32_t dst, const void* src) {
    asm volatile("cp.async.cg.shared.global [%0], [%1], 16;"
                 :: "r"(dst), "l"(src) : "memory");
}
#define MBAR_INIT(a, c) \
    asm volatile("mbarrier.init.shared.b64 [%0], %1;" :: "r"(a), "r"(c) : "memory")
#define MBAR_ARRIVE(a) \
    asm volatile("mbarrier.arrive.shared.b64 _, [%0];" :: "r"(a) : "memory")
#define CPA_MBAR_ARRIVE(a) \
    asm volatile("cp.async.mbarrier.arrive.noinc.shared.b64 [%0];" :: "r"(a) : "memory")

__device__ __forceinline__ void mbar_wait(uint32_t addr, uint32_t parity) {
    asm volatile(
        "{\n\t.reg .pred P;\n\t"
        "W_%=:\n\t"
        "mbarrier.try_wait.parity.acquire.cta.shared::cta.b64 P, [%0], %1, 0x989680;\n\t"
        "@P bra.uni D_%=;\n\t"
        "bra.uni W_%=;\n\t"
        "D_%=:\n\t}"
        :: "r"(addr), "r"(parity) : "memory");
}

__device__ __forceinline__ void ldsm4(uint32_t* d, uint32_t addr) {
    asm volatile("ldmatrix.sync.aligned.m8n8.x4.shared.b16 {%0,%1,%2,%3}, [%4];"
                 : "=r"(d[0]), "=r"(d[1]), "=r"(d[2]), "=r"(d[3]) : "r"(addr));
}
__device__ __forceinline__ uint32_t pack_h2(float lo, float hi) {
    uint32_t r;
    asm("cvt.rn.f16x2.f32 %0, %1, %2;" : "=r"(r) : "f"(hi), "f"(lo));
    return r;
}
__device__ __forceinline__ void mma_f16(float* c, const uint32_t* a,
                                        uint32_t b0, uint32_t b1) {
    asm volatile(
        "mma.sync.aligned.m16n8k16.row.col.f32.f16.f16.f32 "
        "{%0,%1,%2,%3},{%4,%5,%6,%7},{%8,%9},{%0,%1,%2,%3};"
        : "+f"(c[0]), "+f"(c[1]), "+f"(c[2]), "+f"(c[3])
        : "r"(a[0]), "r"(a[1]), "r"(a[2]), "r"(a[3]), "r"(b0), "r"(b1));
}

// ---------------------------------------------------------------------------
// Kernel P: one-shot f32 -> fp16 pre-pass for W.
// ---------------------------------------------------------------------------
__global__ void cvt_f16_kernel(const float4* __restrict__ src,
                               uint4* __restrict__ dst, int n8) {
    for (int i = blockIdx.x * blockDim.x + threadIdx.x; i < n8;
         i += gridDim.x * blockDim.x) {
        float4 v0 = src[2 * i], v1 = src[2 * i + 1];
        uint4 o;
        o.x = pack_h2(v0.x, v0.y);
        o.y = pack_h2(v0.z, v0.w);
        o.z = pack_h2(v1.x, v1.y);
        o.w = pack_h2(v1.z, v1.w);
        dst[i] = o;
    }
}

// ---------------------------------------------------------------------------
// Kernel A: 4-token gate. Phase0 stages x rows in smem + fused f16(x) write.
// Phase1: 16 logits (4 tok x 4 exp) in one pass -> gw read once per 4 tokens.
// Phase2: z for each token's routed expert (repeat experts hit L1).
// 128 threads (4 warps), fp32 throughout -> routing identical to before.
// ---------------------------------------------------------------------------
__global__ __launch_bounds__(128)
void gate_z_kernel(const float* __restrict__ x,
                   const float* __restrict__ gw,
                   const float* __restrict__ bias,
                   const float* __restrict__ lA) {
    extern __shared__ __align__(16) float sx[];        // [TOKB][HID]
    __shared__ float sred[4][32];
    __shared__ float slog[16];
    __shared__ int   s_e[TOKB];

    const int n0   = blockIdx.x * TOKB;
    const int tid  = threadIdx.x;
    const int wid  = tid >> 5;
    const int lane = tid & 31;
    float4* sx4 = reinterpret_cast<float4*>(sx);

    // ---- phase 0: stage 4 x rows + fused fp16 conversion ----
#pragma unroll
    for (int i = 0; i < TOKB * (HID / 4) / 128; i++) {   // 32 iters
        const int idx = tid + i * 128;                   // 0..4095
        const int t   = idx >> 10;
        const int h   = idx & 1023;
        const float4 v = *reinterpret_cast<const float4*>(
            x + (size_t)(n0 + t) * HID + h * 4);
        sx4[idx] = v;
        uint2 o;
        o.x = pack_h2(v.x, v.y);
        o.y = pack_h2(v.z, v.w);
        *reinterpret_cast<uint2*>(g_xh + (size_t)(n0 + t) * HID + h * 4) = o;
    }
    __syncthreads();

    // ---- phase 1: logits[4 tok][4 exp] ----
    float a[16];
#pragma unroll
    for (int i = 0; i < 16; i++) a[i] = 0.f;
    const float4* gw4 = reinterpret_cast<const float4*>(gw);
    for (int h = tid; h < HID / 4; h += 128) {
        float4 xv[TOKB];
#pragma unroll
        for (int t = 0; t < TOKB; t++) xv[t] = sx4[t * (HID / 4) + h];
#pragma unroll
        for (int e = 0; e < NEXP; e++) {
            const float4 g = gw4[e * (HID / 4) + h];
#pragma unroll
            for (int t = 0; t < TOKB; t++)
                a[t * 4 + e] += xv[t].x * g.x + xv[t].y * g.y
                              + xv[t].z * g.z + xv[t].w * g.w;
        }
    }
#pragma unroll
    for (int i = 0; i < 16; i++)
#pragma unroll
        for (int off = 16; off > 0; off >>= 1)
            a[i] += __shfl_xor_sync(0xffffffffu, a[i], off);
    if (lane == 0)
#pragma unroll
        for (int i = 0; i < 16; i++) sred[wid][i] = a[i];
    __syncthreads();
    if (tid < 16)
        slog[tid] = sred[0][tid] + sred[1][tid] + sred[2][tid] + sred[3][tid];
    __syncthreads();
    if (tid < TOKB) {
        float best = -3.4e38f; int be = 0;
#pragma unroll
        for (int e = 0; e < NEXP; e++) {
            const float v = slog[tid * 4 + e] + bias[e];
            if (v > best) { best = v; be = e; }
        }
        s_e[tid] = be;
        g_top1[n0 + tid] = be;
    }
    __syncthreads();

    // ---- phase 2: z[4 tok][8] with routed experts ----
    float z[TOKB][RNK];
#pragma unroll
    for (int t = 0; t < TOKB; t++)
#pragma unroll
        for (int r = 0; r < RNK; r++) z[t][r] = 0.f;
#pragma unroll
    for (int t = 0; t < TOKB; t++) {
        const int e = s_e[t];
        const float4* A4 = reinterpret_cast<const float4*>(
            lA + (size_t)e * RNK * HID);
        for (int h = tid; h < HID / 4; h += 128) {
            const float4 xv = sx4[t * (HID / 4) + h];
#pragma unroll
            for (int r = 0; r < RNK; r++) {
                const float4 g = A4[r * (HID / 4) + h];
                z[t][r] += xv.x * g.x + xv.y * g.y + xv.z * g.z + xv.w * g.w;
            }
        }
    }
#pragma unroll
    for (int t = 0; t < TOKB; t++)
#pragma unroll
        for (int r = 0; r < RNK; r++)
#pragma unroll
            for (int off = 16; off > 0; off >>= 1)
                z[t][r] += __shfl_xor_sync(0xffffffffu, z[t][r], off);
    __syncthreads();
    if (lane == 0)
#pragma unroll
        for (int t = 0; t < TOKB; t++)
#pragma unroll
            for (int r = 0; r < RNK; r++) sred[wid][t * RNK + r] = z[t][r];
    __syncthreads();
    if (tid < 32)
        g_zs[(size_t)(n0 + (tid >> 3)) * RNK + (tid & 7)] =
            sred[0][tid] + sred[1][tid] + sred[2][tid] + sred[3][tid];
}

// ---------------------------------------------------------------------------
// Kernel B: fp16 GEMM (round-12 proven config, unchanged). CTA 128x256x64,
// warp 64x64, 256 threads, 1 CTA/SM, 3-stage mbarrier ring.
// ---------------------------------------------------------------------------
__device__ __forceinline__ void load_chunk(uint32_t base,
                                           const __half* __restrict__ x,
                                           const __half* __restrict__ w,
                                           int m0, int n0, int k0, int tid) {
    const int seg = tid & 7;
    const int r0  = tid >> 3;
    const __half* ga = x + (size_t)(m0 + r0) * HID + k0 + seg * 8;
    const __half* gb = w + (size_t)(n0 + r0) * HID + k0 + seg * 8;
#pragma unroll
    for (int i = 0; i < 4; i++) {
        const uint32_t off = (uint32_t)(r0 + i * 32) * ROWB + seg * 16;
        cp_async16(base + off, ga + (size_t)i * 32 * HID);
    }
#pragma unroll
    for (int i = 0; i < 8; i++) {
        const uint32_t off = (uint32_t)(r0 + i * 32) * ROWB + seg * 16;
        cp_async16(base + A_ST + off, gb + (size_t)i * 32 * HID);
    }
}

__global__ __launch_bounds__(256, 1)
void mma_gemm_kernel(const __half* __restrict__ x,
                     const __half* __restrict__ w,
                     const float* __restrict__ lB,
                     float* __restrict__ out) {
    extern __shared__ __align__(16) char dsm[];
    const uint32_t tiles = smem_u32(dsm);

    __shared__ __align__(8) unsigned long long s_bar[2 * STAGES];
    const uint32_t bfull  = smem_u32(s_bar);
    const uint32_t bempty = bfull + 8 * STAGES;

    const int tid  = threadIdx.x;
    const int wid  = tid >> 5;
    const int lane = tid & 31;
    const int wm   = (wid & 1) * 64;
    const int wn   = (wid >> 1) * 64;
    const int m0   = blockIdx.y * BM;
    const int n0   = blockIdx.x * BN;

    uint32_t aoff[4];
#pragma unroll
    for (int mt = 0; mt < 4; mt++)
        aoff[mt] = (uint32_t)(wm + mt * 16 + (lane & 15)) * ROWB + (lane >> 4) * 16;
    uint32_t boff[8];
#pragma unroll
    for (int nt = 0; nt < 8; nt++)
        boff[nt] = (uint32_t)(A_ST + (wn + nt * 8 + (lane & 7)) * ROWB) + (lane >> 3) * 16;

    float c[4][8][4];
#pragma unroll
    for (int i = 0; i < 4; i++)
#pragma unroll
        for (int j = 0; j < 8; j++)
#pragma unroll
            for (int t = 0; t < 4; t++) c[i][j][t] = 0.f;

    if (tid == 0) {
#pragma unroll
        for (int s = 0; s < STAGES; s++) {
            MBAR_INIT(bfull  + 8 * s, 256);
            MBAR_INIT(bempty + 8 * s, 256);
        }
    }
    __syncthreads();

    load_chunk(tiles + 0 * STAGE_BYTES, x, w, m0, n0, 0 * BK, tid);
    CPA_MBAR_ARRIVE(bfull + 0);
    load_chunk(tiles + 1 * STAGE_BYTES, x, w, m0, n0, 1 * BK, tid);
    CPA_MBAR_ARRIVE(bfull + 8);

    uint32_t Bf[8][4], A0[4][4], A1[4][4];

#define SLOT(S, S2, PF, PE, DOWAIT, KK)                                        \
    if ((KK) < NCHUNK) {                                                       \
        mbar_wait(bfull + 8 * (S), (PF));                                      \
        const uint32_t sbase = tiles + (S) * STAGE_BYTES;                      \
        _Pragma("unroll")                                                      \
        for (int nt = 0; nt < 8; nt++) ldsm4(Bf[nt], sbase + boff[nt]);        \
        _Pragma("unroll")                                                      \
        for (int mt = 0; mt < 4; mt++) ldsm4(A0[mt], sbase + aoff[mt]);        \
        _Pragma("unroll")                                                      \
        for (int mt = 0; mt < 4; mt++) ldsm4(A1[mt], sbase + aoff[mt] + 32);   \
        _Pragma("unroll")                                                      \
        for (int mt = 0; mt < 4; mt++)                                         \
            _Pragma("unroll")                                                  \
            for (int nt = 0; nt < 8; nt++)                                     \
                mma_f16(c[mt][nt], A0[mt], Bf[nt][0], Bf[nt][1]);              \
        if ((KK) + 2 < NCHUNK) {                                               \
            if (DOWAIT) mbar_wait(bempty + 8 * (S2), (PE));                    \
            load_chunk(tiles + (S2) * STAGE_BYTES, x, w, m0, n0,               \
                       ((KK) + 2) * BK, tid);                                  \
            CPA_MBAR_ARRIVE(bfull + 8 * (S2));                                 \
        }                                                                      \
        _Pragma("unroll")                                                      \
        for (int mt = 0; mt < 4; mt++) ldsm4(A0[mt], sbase + aoff[mt] + 64);   \
        _Pragma("unroll")                                                      \
        for (int mt = 0; mt < 4; mt++)                                         \
            _Pragma("unroll")                                                  \
            for (int nt = 0; nt < 8; nt++)                                     \
                mma_f16(c[mt][nt], A1[mt], Bf[nt][2], Bf[nt][3]);              \
        _Pragma("unroll")                                                      \
        for (int nt = 0; nt < 8; nt++) ldsm4(Bf[nt], sbase + boff[nt] + 64);   \
        _Pragma("unroll")                                                      \
        for (int mt = 0; mt < 4; mt++) ldsm4(A1[mt], sbase + aoff[mt] + 96);   \
        _Pragma("unroll")                                                      \
        for (int mt = 0; mt < 4; mt++)                                         \
            _Pragma("unroll")                                                  \
            for (int nt = 0; nt < 8; nt++)                                     \
                mma_f16(c[mt][nt], A0[mt], Bf[nt][0], Bf[nt][1]);              \
        MBAR_ARRIVE(bempty + 8 * (S));                                         \
        _Pragma("unroll")                                                      \
        for (int mt = 0; mt < 4; mt++)                                         \
            _Pragma("unroll")                                                  \
            for (int nt = 0; nt < 8; nt++)                                     \
                mma_f16(c[mt][nt], A1[mt], Bf[nt][2], Bf[nt][3]);              \
    }

    for (int j = 0; j < NROUND; j++) {
        const uint32_t pf = (uint32_t)(j & 1);
        const uint32_t pm = (uint32_t)((j - 1) & 1);
        SLOT(0, 2, pf, pm, (j >= 1), 3 * j + 0);
        SLOT(1, 0, pf, pf, true,     3 * j + 1);
        SLOT(2, 1, pf, pf, true,     3 * j + 2);
    }
#undef SLOT

    // ---- epilogue: add LoRA delta, write out ----
    const int rowg = lane >> 2;
    const int colg = (lane & 3) * 2;
#pragma unroll
    for (int mt = 0; mt < 4; mt++) {
#pragma unroll
        for (int hr = 0; hr < 2; hr++) {
            const int row = m0 + wm + mt * 16 + hr * 8 + rowg;
            const int e   = g_top1[row];
            const float4* zz = reinterpret_cast<const float4*>(g_zs + (size_t)row * RNK);
            const float4 z0 = zz[0], z1 = zz[1];
            const float* lbe = lB + (size_t)e * HID * RNK;
            float* orow = out + (size_t)row * HID;
#pragma unroll
            for (int nt = 0; nt < 8; nt++) {
                const int col = n0 + wn + nt * 8 + colg;
                const float4* bp =
                    reinterpret_cast<const float4*>(lbe + (size_t)col * RNK);
                const float4 b0 = bp[0], b1 = bp[1];
                const float4* bq =
                    reinterpret_cast<const float4*>(lbe + (size_t)(col + 1) * RNK);
                const float4 q0 = bq[0], q1 = bq[1];
                float d0 = z0.x * b0.x + z0.y * b0.y + z0.z * b0.z + z0.w * b0.w
                         + z1.x * b1.x + z1.y * b1.y + z1.z * b1.z + z1.w * b1.w;
                float d1 = z0.x * q0.x + z0.y * q0.y + z0.z * q0.z + z0.w * q0.w
                         + z1.x * q1.x + z1.y * q1.y + z1.z * q1.z + z1.w * q1.w;
                float2 res = make_float2(c[mt][nt][hr * 2 + 0] + d0,
                                         c[mt][nt][hr * 2 + 1] + d1);
                *reinterpret_cast<float2*>(orow + col) = res;
            }
        }
    }
}

// ---------------------------------------------------------------------------
extern "C" void kernel_launch(void* const* d_in, const int* in_sizes, int n_in,
                              void* d_out, int out_size) {
    const float* x    = (const float*)d_in[0];
    const float* W_up = (const float*)d_in[1];
    const float* gw   = (const float*)d_in[2];
    const float* bias = (const float*)d_in[3];
    const float* lA   = (const float*)d_in[4];
    const float* lBm  = (const float*)d_in[5];
    float* out        = (float*)d_out;

    const int N = in_sizes[0] / HID;   // 16384 tokens

    cudaFuncSetAttribute(mma_gemm_kernel,
                         cudaFuncAttributeMaxDynamicSharedMemorySize, DYN_SMEM);
    cudaFuncSetAttribute(mma_gemm_kernel,
                         cudaFuncAttributePreferredSharedMemoryCarveout, 100);
    cudaFuncSetAttribute(gate_z_kernel,
                         cudaFuncAttributeMaxDynamicSharedMemorySize, GATE_SMEM);

    __half* xh = nullptr;
    __half* wh = nullptr;
    cudaGetSymbolAddress((void**)&xh, g_xh);
    cudaGetSymbolAddress((void**)&wh, g_wh);

    cvt_f16_kernel<<<2048, 256>>>((const float4*)W_up, (uint4*)wh, HID * HID / 8);
    gate_z_kernel<<<N / TOKB, 128, GATE_SMEM>>>(x, gw, bias, lA);

    dim3 grid(HID / BN, N / BM);       // (16, 128)
    mma_gemm_kernel<<<grid, 256, DYN_SMEM>>>(xh, wh, lBm, out);
}

// round 16
// speedup vs baseline: 1.5774x; 1.5774x over previous
#include <cuda_runtime.h>
#include <cuda_fp16.h>
#include <cstdint>

// ---------------- problem constants ----------------
#define HID   4096
#define NEXP  4
#define RNK   8
#define MAXN  16384

// ---------------- GEMM tiling (fp16 operands) ----------------
#define BM 128
#define BN 256
#define BK 64
#define NCHUNK (HID / BK)             // 64
#define ROWB   144
#define A_ST   (BM * ROWB)            // 18432
#define B_ST   (BN * ROWB)            // 36864
#define STAGE_BYTES (A_ST + B_ST)     // 55296
#define STAGES 3
#define DYN_SMEM (STAGES * STAGE_BYTES)   // 165888
#define NROUND ((NCHUNK + 2) / 3)     // 22

// scratch (allocation-free rule: __device__ globals live in bss)
__device__ float   g_zs[MAXN * RNK];
__device__ int     g_top1[MAXN];
__device__ __half  g_xh[(size_t)MAXN * HID];   // fp16 x   (128 MB)
__device__ __half  g_wh[(size_t)HID * HID];    // fp16 W   (32 MB)

// ---------------- PTX helpers ----------------
__device__ __forceinline__ uint32_t smem_u32(const void* p) {
    uint32_t a;
    asm("{ .reg .u64 t; cvta.to.shared.u64 t, %1; cvt.u32.u64 %0, t; }"
        : "=r"(a) : "l"(p));
    return a;
}
__device__ __forceinline__ void cp_async16(uint32_t dst, const void* src) {
    asm volatile("cp.async.cg.shared.global [%0], [%1], 16;"
                 :: "r"(dst), "l"(src) : "memory");
}
#define MBAR_INIT(a, c) \
    asm volatile("mbarrier.init.shared.b64 [%0], %1;" :: "r"(a), "r"(c) : "memory")
#define MBAR_ARRIVE(a) \
    asm volatile("mbarrier.arrive.shared.b64 _, [%0];" :: "r"(a) : "memory")
#define CPA_MBAR_ARRIVE(a) \
    asm volatile("cp.async.mbarrier.arrive.noinc.shared.b64 [%0];" :: "r"(a) : "memory")

__device__ __forceinline__ void mbar_wait(uint32_t addr, uint32_t parity) {
    asm volatile(
        "{\n\t.reg .pred P;\n\t"
        "W_%=:\n\t"
        "mbarrier.try_wait.parity.acquire.cta.shared::cta.b64 P, [%0], %1, 0x989680;\n\t"
        "@P bra.uni D_%=;\n\t"
        "bra.uni W_%=;\n\t"
        "D_%=:\n\t}"
        :: "r"(addr), "r"(parity) : "memory");
}

__device__ __forceinline__ void ldsm4(uint32_t* d, uint32_t addr) {
    asm volatile("ldmatrix.sync.aligned.m8n8.x4.shared.b16 {%0,%1,%2,%3}, [%4];"
                 : "=r"(d[0]), "=r"(d[1]), "=r"(d[2]), "=r"(d[3]) : "r"(addr));
}
__device__ __forceinline__ uint32_t pack_h2(float lo, float hi) {
    uint32_t r;
    asm("cvt.rn.f16x2.f32 %0, %1, %2;" : "=r"(r) : "f"(hi), "f"(lo));
    return r;
}
__device__ __forceinline__ void mma_f16(float* c, const uint32_t* a,
                                        uint32_t b0, uint32_t b1) {
    asm volatile(
        "mma.sync.aligned.m16n8k16.row.col.f32.f16.f16.f32 "
        "{%0,%1,%2,%3},{%4,%5,%6,%7},{%8,%9},{%0,%1,%2,%3};"
        : "+f"(c[0]), "+f"(c[1]), "+f"(c[2]), "+f"(c[3])
        : "r"(a[0]), "r"(a[1]), "r"(a[2]), "r"(a[3]), "r"(b0), "r"(b1));
}

// ---------------------------------------------------------------------------
// Kernel P: one-shot f32 -> fp16 pre-pass for W.
// ---------------------------------------------------------------------------
__global__ void cvt_f16_kernel(const float4* __restrict__ src,
                               uint4* __restrict__ dst, int n8) {
    for (int i = blockIdx.x * blockDim.x + threadIdx.x; i < n8;
         i += gridDim.x * blockDim.x) {
        float4 v0 = src[2 * i], v1 = src[2 * i + 1];
        uint4 o;
        o.x = pack_h2(v0.x, v0.y);
        o.y = pack_h2(v0.z, v0.w);
        o.z = pack_h2(v1.x, v1.y);
        o.w = pack_h2(v1.z, v1.w);
        dst[i] = o;
    }
}

// ---------------------------------------------------------------------------
// Kernel A: per-token gating + LoRA z (round-12 proven version).
// x row cached in smem, fused f16(x) conversion, fp32 routing math.
// ---------------------------------------------------------------------------
__global__ void gate_z_kernel(const float* __restrict__ x,
                              const float* __restrict__ gw,
                              const float* __restrict__ bias,
                              const float* __restrict__ lA) {
    const int n    = blockIdx.x;
    const int tid  = threadIdx.x;
    const int wid  = tid >> 5;
    const int lane = tid & 31;

    __shared__ float sx[HID];
    __shared__ float sred[4][RNK];
    __shared__ int   s_e;
    float4* sx4 = reinterpret_cast<float4*>(sx);

    const float4* xr = reinterpret_cast<const float4*>(x + (size_t)n * HID);
    uint2* xh2 = reinterpret_cast<uint2*>(g_xh + (size_t)n * HID);

    float a[NEXP] = {0.f, 0.f, 0.f, 0.f};
    const float4* gw4 = reinterpret_cast<const float4*>(gw);
    for (int h = tid; h < HID / 4; h += 128) {
        float4 xv = xr[h];
        sx4[h] = xv;
        uint2 o;
        o.x = pack_h2(xv.x, xv.y);
        o.y = pack_h2(xv.z, xv.w);
        xh2[h] = o;
#pragma unroll
        for (int e = 0; e < NEXP; e++) {
            float4 g = gw4[e * (HID / 4) + h];
            a[e] += xv.x * g.x + xv.y * g.y + xv.z * g.z + xv.w * g.w;
        }
    }
#pragma unroll
    for (int e = 0; e < NEXP; e++)
#pragma unroll
        for (int off = 16; off > 0; off >>= 1)
            a[e] += __shfl_xor_sync(0xffffffffu, a[e], off);
    if (lane == 0)
#pragma unroll
        for (int e = 0; e < NEXP; e++) sred[wid][e] = a[e];
    __syncthreads();
    if (tid == 0) {
        float best = -3.4e38f; int be = 0;
#pragma unroll
        for (int e = 0; e < NEXP; e++) {
            float v = sred[0][e] + sred[1][e] + sred[2][e] + sred[3][e] + bias[e];
            if (v > best) { best = v; be = e; }
        }
        s_e = be;
        g_top1[n] = be;
    }
    __syncthreads();

    const int e = s_e;
    const float4* A4 = reinterpret_cast<const float4*>(lA + (size_t)e * RNK * HID);
    float z[RNK];
#pragma unroll
    for (int r = 0; r < RNK; r++) z[r] = 0.f;
    for (int h = tid; h < HID / 4; h += 128) {
        float4 xv = sx4[h];
#pragma unroll
        for (int r = 0; r < RNK; r++) {
            float4 g = A4[r * (HID / 4) + h];
            z[r] += xv.x * g.x + xv.y * g.y + xv.z * g.z + xv.w * g.w;
        }
    }
#pragma unroll
    for (int r = 0; r < RNK; r++)
#pragma unroll
        for (int off = 16; off > 0; off >>= 1)
            z[r] += __shfl_xor_sync(0xffffffffu, z[r], off);
    __syncthreads();
    if (lane == 0)
#pragma unroll
        for (int r = 0; r < RNK; r++) sred[wid][r] = z[r];
    __syncthreads();
    if (tid < RNK)
        g_zs[(size_t)n * RNK + tid] =
            sred[0][tid] + sred[1][tid] + sred[2][tid] + sred[3][tid];
}

// ---------------------------------------------------------------------------
// Kernel B: fp16 GEMM (round-12 proven config, unchanged). CTA 128x256x64,
// warp 64x64, 256 threads, 1 CTA/SM, 3-stage mbarrier ring.
// ---------------------------------------------------------------------------
__device__ __forceinline__ void load_chunk(uint32_t base,
                                           const __half* __restrict__ x,
                                           const __half* __restrict__ w,
                                           int m0, int n0, int k0, int tid) {
    const int seg = tid & 7;
    const int r0  = tid >> 3;
    const __half* ga = x + (size_t)(m0 + r0) * HID + k0 + seg * 8;
    const __half* gb = w + (size_t)(n0 + r0) * HID + k0 + seg * 8;
#pragma unroll
    for (int i = 0; i < 4; i++) {
        const uint32_t off = (uint32_t)(r0 + i * 32) * ROWB + seg * 16;
        cp_async16(base + off, ga + (size_t)i * 32 * HID);
    }
#pragma unroll
    for (int i = 0; i < 8; i++) {
        const uint32_t off = (uint32_t)(r0 + i * 32) * ROWB + seg * 16;
        cp_async16(base + A_ST + off, gb + (size_t)i * 32 * HID);
    }
}

__global__ __launch_bounds__(256, 1)
void mma_gemm_kernel(const __half* __restrict__ x,
                     const __half* __restrict__ w,
                     const float* __restrict__ lB,
                     float* __restrict__ out) {
    extern __shared__ __align__(16) char dsm[];
    const uint32_t tiles = smem_u32(dsm);

    __shared__ __align__(8) unsigned long long s_bar[2 * STAGES];
    const uint32_t bfull  = smem_u32(s_bar);
    const uint32_t bempty = bfull + 8 * STAGES;

    const int tid  = threadIdx.x;
    const int wid  = tid >> 5;
    const int lane = tid & 31;
    const int wm   = (wid & 1) * 64;
    const int wn   = (wid >> 1) * 64;
    const int m0   = blockIdx.y * BM;
    const int n0   = blockIdx.x * BN;

    uint32_t aoff[4];
#pragma unroll
    for (int mt = 0; mt < 4; mt++)
        aoff[mt] = (uint32_t)(wm + mt * 16 + (lane & 15)) * ROWB + (lane >> 4) * 16;
    uint32_t boff[8];
#pragma unroll
    for (int nt = 0; nt < 8; nt++)
        boff[nt] = (uint32_t)(A_ST + (wn + nt * 8 + (lane & 7)) * ROWB) + (lane >> 3) * 16;

    float c[4][8][4];
#pragma unroll
    for (int i = 0; i < 4; i++)
#pragma unroll
        for (int j = 0; j < 8; j++)
#pragma unroll
            for (int t = 0; t < 4; t++) c[i][j][t] = 0.f;

    if (tid == 0) {
#pragma unroll
        for (int s = 0; s < STAGES; s++) {
            MBAR_INIT(bfull  + 8 * s, 256);
            MBAR_INIT(bempty + 8 * s, 256);
        }
    }
    __syncthreads();

    load_chunk(tiles + 0 * STAGE_BYTES, x, w, m0, n0, 0 * BK, tid);
    CPA_MBAR_ARRIVE(bfull + 0);
    load_chunk(tiles + 1 * STAGE_BYTES, x, w, m0, n0, 1 * BK, tid);
    CPA_MBAR_ARRIVE(bfull + 8);

    uint32_t Bf[8][4], A0[4][4], A1[4][4];

#define SLOT(S, S2, PF, PE, DOWAIT, KK)                                        \
    if ((KK) < NCHUNK) {                                                       \
        mbar_wait(bfull + 8 * (S), (PF));                                      \
        const uint32_t sbase = tiles + (S) * STAGE_BYTES;                      \
        _Pragma("unroll")                                                      \
        for (int nt = 0; nt < 8; nt++) ldsm4(Bf[nt], sbase + boff[nt]);        \
        _Pragma("unroll")                                                      \
        for (int mt = 0; mt < 4; mt++) ldsm4(A0[mt], sbase + aoff[mt]);        \
        _Pragma("unroll")                                                      \
        for (int mt = 0; mt < 4; mt++) ldsm4(A1[mt], sbase + aoff[mt] + 32);   \
        _Pragma("unroll")                                                      \
        for (int mt = 0; mt < 4; mt++)                                         \
            _Pragma("unroll")                                                  \
            for (int nt = 0; nt < 8; nt++)                                     \
                mma_f16(c[mt][nt], A0[mt], Bf[nt][0], Bf[nt][1]);              \
        if ((KK) + 2 < NCHUNK) {                                               \
            if (DOWAIT) mbar_wait(bempty + 8 * (S2), (PE));                    \
            load_chunk(tiles + (S2) * STAGE_BYTES, x, w, m0, n0,               \
                       ((KK) + 2) * BK, tid);                                  \
            CPA_MBAR_ARRIVE(bfull + 8 * (S2));                                 \
        }                                                                      \
        _Pragma("unroll")                                                      \
        for (int mt = 0; mt < 4; mt++) ldsm4(A0[mt], sbase + aoff[mt] + 64);   \
        _Pragma("unroll")                                                      \
        for (int mt = 0; mt < 4; mt++)                                         \
            _Pragma("unroll")                                                  \
            for (int nt = 0; nt < 8; nt++)                                     \
                mma_f16(c[mt][nt], A1[mt], Bf[nt][2], Bf[nt][3]);              \
        _Pragma("unroll")                                                      \
        for (int nt = 0; nt < 8; nt++) ldsm4(Bf[nt], sbase + boff[nt] + 64);   \
        _Pragma("unroll")                                                      \
        for (int mt = 0; mt < 4; mt++) ldsm4(A1[mt], sbase + aoff[mt] + 96);   \
        _Pragma("unroll")                                                      \
        for (int mt = 0; mt < 4; mt++)                                         \
            _Pragma("unroll")                                                  \
            for (int nt = 0; nt < 8; nt++)                                     \
                mma_f16(c[mt][nt], A0[mt], Bf[nt][0], Bf[nt][1]);              \
        MBAR_ARRIVE(bempty + 8 * (S));                                         \
        _Pragma("unroll")                                                      \
        for (int mt = 0; mt < 4; mt++)                                         \
            _Pragma("unroll")                                                  \
            for (int nt = 0; nt < 8; nt++)                                     \
                mma_f16(c[mt][nt], A1[mt], Bf[nt][2], Bf[nt][3]);              \
    }

    for (int j = 0; j < NROUND; j++) {
        const uint32_t pf = (uint32_t)(j & 1);
        const uint32_t pm = (uint32_t)((j - 1) & 1);
        SLOT(0, 2, pf, pm, (j >= 1), 3 * j + 0);
        SLOT(1, 0, pf, pf, true,     3 * j + 1);
        SLOT(2, 1, pf, pf, true,     3 * j + 2);
    }
#undef SLOT

    // ---- epilogue: add LoRA delta, write out ----
    const int rowg = lane >> 2;
    const int colg = (lane & 3) * 2;
#pragma unroll
    for (int mt = 0; mt < 4; mt++) {
#pragma unroll
        for (int hr = 0; hr < 2; hr++) {
            const int row = m0 + wm + mt * 16 + hr * 8 + rowg;
            const int e   = g_top1[row];
            const float4* zz = reinterpret_cast<const float4*>(g_zs + (size_t)row * RNK);
            const float4 z0 = zz[0], z1 = zz[1];
            const float* lbe = lB + (size_t)e * HID * RNK;
            float* orow = out + (size_t)row * HID;
#pragma unroll
            for (int nt = 0; nt < 8; nt++) {
                const int col = n0 + wn + nt * 8 + colg;
                const float4* bp =
                    reinterpret_cast<const float4*>(lbe + (size_t)col * RNK);
                const float4 b0 = bp[0], b1 = bp[1];
                const float4* bq =
                    reinterpret_cast<const float4*>(lbe + (size_t)(col + 1) * RNK);
                const float4 q0 = bq[0], q1 = bq[1];
                float d0 = z0.x * b0.x + z0.y * b0.y + z0.z * b0.z + z0.w * b0.w
                         + z1.x * b1.x + z1.y * b1.y + z1.z * b1.z + z1.w * b1.w;
                float d1 = z0.x * q0.x + z0.y * q0.y + z0.z * q0.z + z0.w * q0.w
                         + z1.x * q1.x + z1.y * q1.y + z1.z * q1.z + z1.w * q1.w;
                float2 res = make_float2(c[mt][nt][hr * 2 + 0] + d0,
                                         c[mt][nt][hr * 2 + 1] + d1);
                *reinterpret_cast<float2*>(orow + col) = res;
            }
        }
    }
}

// ---------------------------------------------------------------------------
extern "C" void kernel_launch(void* const* d_in, const int* in_sizes, int n_in,
                              void* d_out, int out_size) {
    const float* x    = (const float*)d_in[0];
    const float* W_up = (const float*)d_in[1];
    const float* gw   = (const float*)d_in[2];
    const float* bias = (const float*)d_in[3];
    const float* lA   = (const float*)d_in[4];
    const float* lBm  = (const float*)d_in[5];
    float* out        = (float*)d_out;

    const int N = in_sizes[0] / HID;   // 16384 tokens

    // one-time setup (first call is the uncaptured correctness run)
    static cudaStream_t s2 = nullptr;
    static cudaEvent_t  evFork = nullptr, evJoin = nullptr;
    if (s2 == nullptr) {
        cudaStreamCreateWithFlags(&s2, cudaStreamNonBlocking);
        cudaEventCreateWithFlags(&evFork, cudaEventDisableTiming);
        cudaEventCreateWithFlags(&evJoin, cudaEventDisableTiming);
        cudaFuncSetAttribute(mma_gemm_kernel,
                             cudaFuncAttributeMaxDynamicSharedMemorySize, DYN_SMEM);
        cudaFuncSetAttribute(mma_gemm_kernel,
                             cudaFuncAttributePreferredSharedMemoryCarveout, 100);
    }

    __half* xh = nullptr;
    __half* wh = nullptr;
    cudaGetSymbolAddress((void**)&xh, g_xh);
    cudaGetSymbolAddress((void**)&wh, g_wh);

    // fork: cvt_W on s2 runs concurrently with gate_z on the main stream
    cudaEventRecord(evFork, 0);
    cudaStreamWaitEvent(s2, evFork, 0);
    cvt_f16_kernel<<<2048, 256, 0, s2>>>((const float4*)W_up, (uint4*)wh,
                                         HID * HID / 8);
    cudaEventRecord(evJoin, s2);

    gate_z_kernel<<<N, 128>>>(x, gw, bias, lA);

    // join: GEMM needs both g_xh (gate) and g_wh (cvt)
    cudaStreamWaitEvent(0, evJoin, 0);

    dim3 grid(HID / BN, N / BM);       // (16, 128)
    mma_gemm_kernel<<<grid, 256, DYN_SMEM>>>(xh, wh, lBm, out);
}

// round 17
// speedup vs baseline: 1.6234x; 1.0291x over previous
#include <cuda_runtime.h>
#include <cuda_fp16.h>
#include <cstdint>

// ---------------- problem constants ----------------
#define HID   4096
#define NEXP  4
#define RNK   8
#define MAXN  16384
#define ZCOLS (NEXP * RNK)            // 32

// ---------------- GEMM tiling (fp16 operands) ----------------
#define BM 128
#define BN 256
#define BK 64
#define NCHUNK (HID / BK)             // 64
#define ROWB   144
#define A_ST   (BM * ROWB)            // 18432
#define B_ST   (BN * ROWB)            // 36864
#define STAGE_BYTES (A_ST + B_ST)     // 55296
#define STAGES 3
#define DYN_SMEM (STAGES * STAGE_BYTES)   // 165888
#define NROUND ((NCHUNK + 2) / 3)     // 22

// ---------------- z skinny GEMM tiling ----------------
#define ZA_ST (BM * ROWB)             // 18432
#define ZB_ST (ZCOLS * ROWB)          // 4608
#define ZSTAGE (ZA_ST + ZB_ST)        // 23040
#define ZSMEM (3 * ZSTAGE)            // 69120

// scratch (allocation-free rule: __device__ globals live in bss)
__device__ float   g_zs[MAXN * RNK];
__device__ int     g_top1[MAXN];
__device__ __half  g_xh[(size_t)MAXN * HID];   // fp16 x   (128 MB)
__device__ __half  g_wh[(size_t)HID * HID];    // fp16 W   (32 MB)
__device__ __half  g_lAh[ZCOLS * HID];         // fp16 lora_A (256 KB)

// ---------------- PTX helpers ----------------
__device__ __forceinline__ uint32_t smem_u32(const void* p) {
    uint32_t a;
    asm("{ .reg .u64 t; cvta.to.shared.u64 t, %1; cvt.u32.u64 %0, t; }"
        : "=r"(a) : "l"(p));
    return a;
}
__device__ __forceinline__ void cp_async16(uint32_t dst, const void* src) {
    asm volatile("cp.async.cg.shared.global [%0], [%1], 16;"
                 :: "r"(dst), "l"(src) : "memory");
}
#define CP_COMMIT() asm volatile("cp.async.commit_group;" ::: "memory")
#define CP_WAIT1()  asm volatile("cp.async.wait_group 1;"  ::: "memory")
#define MBAR_INIT(a, c) \
    asm volatile("mbarrier.init.shared.b64 [%0], %1;" :: "r"(a), "r"(c) : "memory")
#define MBAR_ARRIVE(a) \
    asm volatile("mbarrier.arrive.shared.b64 _, [%0];" :: "r"(a) : "memory")
#define CPA_MBAR_ARRIVE(a) \
    asm volatile("cp.async.mbarrier.arrive.noinc.shared.b64 [%0];" :: "r"(a) : "memory")

__device__ __forceinline__ void mbar_wait(uint32_t addr, uint32_t parity) {
    asm volatile(
        "{\n\t.reg .pred P;\n\t"
        "W_%=:\n\t"
        "mbarrier.try_wait.parity.acquire.cta.shared::cta.b64 P, [%0], %1, 0x989680;\n\t"
        "@P bra.uni D_%=;\n\t"
        "bra.uni W_%=;\n\t"
        "D_%=:\n\t}"
        :: "r"(addr), "r"(parity) : "memory");
}

__device__ __forceinline__ void ldsm4(uint32_t* d, uint32_t addr) {
    asm volatile("ldmatrix.sync.aligned.m8n8.x4.shared.b16 {%0,%1,%2,%3}, [%4];"
                 : "=r"(d[0]), "=r"(d[1]), "=r"(d[2]), "=r"(d[3]) : "r"(addr));
}
__device__ __forceinline__ uint32_t pack_h2(float lo, float hi) {
    uint32_t r;
    asm("cvt.rn.f16x2.f32 %0, %1, %2;" : "=r"(r) : "f"(hi), "f"(lo));
    return r;
}
__device__ __forceinline__ void mma_f16(float* c, const uint32_t* a,
                                        uint32_t b0, uint32_t b1) {
    asm volatile(
        "mma.sync.aligned.m16n8k16.row.col.f32.f16.f16.f32 "
        "{%0,%1,%2,%3},{%4,%5,%6,%7},{%8,%9},{%0,%1,%2,%3};"
        : "+f"(c[0]), "+f"(c[1]), "+f"(c[2]), "+f"(c[3])
        : "r"(a[0]), "r"(a[1]), "r"(a[2]), "r"(a[3]), "r"(b0), "r"(b1));
}

// ---------------------------------------------------------------------------
// Kernel P: one-shot f32 -> fp16 pre-pass (used for W and lora_A).
// ---------------------------------------------------------------------------
__global__ void cvt_f16_kernel(const float4* __restrict__ src,
                               uint4* __restrict__ dst, int n8) {
    for (int i = blockIdx.x * blockDim.x + threadIdx.x; i < n8;
         i += gridDim.x * blockDim.x) {
        float4 v0 = src[2 * i], v1 = src[2 * i + 1];
        uint4 o;
        o.x = pack_h2(v0.x, v0.y);
        o.y = pack_h2(v0.z, v0.w);
        o.z = pack_h2(v1.x, v1.y);
        o.w = pack_h2(v1.z, v1.w);
        dst[i] = o;
    }
}

// ---------------------------------------------------------------------------
// Kernel A: gate_light — per-token logits + argmax + fused f16(x) write.
// (Round-12 gate minus the lA phase; routing math bit-identical fp32.)
// ---------------------------------------------------------------------------
__global__ void gate_light_kernel(const float* __restrict__ x,
                                  const float* __restrict__ gw,
                                  const float* __restrict__ bias) {
    const int n    = blockIdx.x;
    const int tid  = threadIdx.x;
    const int wid  = tid >> 5;
    const int lane = tid & 31;

    __shared__ float sred[4][NEXP];

    const float4* xr = reinterpret_cast<const float4*>(x + (size_t)n * HID);
    uint2* xh2 = reinterpret_cast<uint2*>(g_xh + (size_t)n * HID);

    float a[NEXP] = {0.f, 0.f, 0.f, 0.f};
    const float4* gw4 = reinterpret_cast<const float4*>(gw);
    for (int h = tid; h < HID / 4; h += 128) {
        float4 xv = xr[h];
        uint2 o;
        o.x = pack_h2(xv.x, xv.y);
        o.y = pack_h2(xv.z, xv.w);
        xh2[h] = o;
#pragma unroll
        for (int e = 0; e < NEXP; e++) {
            float4 g = gw4[e * (HID / 4) + h];
            a[e] += xv.x * g.x + xv.y * g.y + xv.z * g.z + xv.w * g.w;
        }
    }
#pragma unroll
    for (int e = 0; e < NEXP; e++)
#pragma unroll
        for (int off = 16; off > 0; off >>= 1)
            a[e] += __shfl_xor_sync(0xffffffffu, a[e], off);
    if (lane == 0)
#pragma unroll
        for (int e = 0; e < NEXP; e++) sred[wid][e] = a[e];
    __syncthreads();
    if (tid == 0) {
        float best = -3.4e38f; int be = 0;
#pragma unroll
        for (int e = 0; e < NEXP; e++) {
            float v = sred[0][e] + sred[1][e] + sred[2][e] + sred[3][e] + bias[e];
            if (v > best) { best = v; be = e; }
        }
        g_top1[n] = be;
    }
}

// ---------------------------------------------------------------------------
// Kernel Z: skinny tensor-core GEMM  Z[N,32] = xh . lAh^T, epilogue selects
// the routed expert's 8 columns into g_zs. CTA: 128 tokens, 256 threads,
// 8 warps each 16 rows x 32 cols. 3-stage cp.async, R9-style single barrier.
// ---------------------------------------------------------------------------
__global__ __launch_bounds__(256)
void zgemm_kernel(const __half* __restrict__ xh) {
    extern __shared__ __align__(16) char zsm[];
    const uint32_t tiles = smem_u32(zsm);

    const int tid  = threadIdx.x;
    const int wid  = tid >> 5;
    const int lane = tid & 31;
    const int m0   = blockIdx.x * BM;
    const int wm   = wid * 16;

    const uint32_t aoff = (uint32_t)(wm + (lane & 15)) * ROWB + (lane >> 4) * 16;
    uint32_t boff[4];
#pragma unroll
    for (int nt = 0; nt < 4; nt++)
        boff[nt] = (uint32_t)(ZA_ST + (nt * 8 + (lane & 7)) * ROWB) + (lane >> 3) * 16;

    float c[4][4];
#pragma unroll
    for (int i = 0; i < 4; i++)
#pragma unroll
        for (int t = 0; t < 4; t++) c[i][t] = 0.f;

    // chunk loader: A 128 rows (4/thread), B 32 rows (1 per 256... 8 segs*32=256)
    auto load_chunk = [&](uint32_t base, int k0) {
        const int seg = tid & 7;
        const int r0  = tid >> 3;            // 0..31
        const __half* ga = xh + (size_t)(m0 + r0) * HID + k0 + seg * 8;
#pragma unroll
        for (int i = 0; i < 4; i++) {
            const uint32_t off = (uint32_t)(r0 + i * 32) * ROWB + seg * 16;
            cp_async16(base + off, ga + (size_t)i * 32 * HID);
        }
        // B: 32 rows x 8 segs = 256 transfers, exactly one per thread
        const __half* gb = g_lAh + (size_t)r0 * HID + k0 + seg * 8;
        cp_async16(base + ZA_ST + (uint32_t)r0 * ROWB + seg * 16, gb);
    };

    load_chunk(tiles + 0 * ZSTAGE, 0 * BK);
    CP_COMMIT();
    load_chunk(tiles + 1 * ZSTAGE, 1 * BK);
    CP_COMMIT();

    for (int k = 0; k < NCHUNK; k++) {
        CP_WAIT1();
        __syncthreads();
        if (k + 2 < NCHUNK)
            load_chunk(tiles + ((k + 2) % 3) * ZSTAGE, (k + 2) * BK);
        CP_COMMIT();

        const uint32_t sbase = tiles + (k % 3) * ZSTAGE;
#pragma unroll
        for (int h = 0; h < 2; h++) {
            uint32_t Bf[4][4];
#pragma unroll
            for (int nt = 0; nt < 4; nt++)
                ldsm4(Bf[nt], sbase + boff[nt] + h * 64);
#pragma unroll
            for (int ks = 0; ks < 2; ks++) {
                uint32_t Af[4];
                ldsm4(Af, sbase + aoff + (h * 2 + ks) * 32);
#pragma unroll
                for (int nt = 0; nt < 4; nt++)
                    mma_f16(c[nt], Af, Bf[nt][2 * ks], Bf[nt][2 * ks + 1]);
            }
        }
    }

    // epilogue: col = e*8 + r  (lA row order), select routed expert
    const int rowg = lane >> 2;
    const int colg = (lane & 3) * 2;
#pragma unroll
    for (int hr = 0; hr < 2; hr++) {
        const int row = m0 + wm + hr * 8 + rowg;
        const int e   = g_top1[row];
        g_zs[(size_t)row * RNK + colg]     = c[e][hr * 2 + 0];
        g_zs[(size_t)row * RNK + colg + 1] = c[e][hr * 2 + 1];
    }
}

// ---------------------------------------------------------------------------
// Kernel B: fp16 GEMM (round-12 proven config, unchanged).
// ---------------------------------------------------------------------------
__device__ __forceinline__ void load_chunk(uint32_t base,
                                           const __half* __restrict__ x,
                                           const __half* __restrict__ w,
                                           int m0, int n0, int k0, int tid) {
    const int seg = tid & 7;
    const int r0  = tid >> 3;
    const __half* ga = x + (size_t)(m0 + r0) * HID + k0 + seg * 8;
    const __half* gb = w + (size_t)(n0 + r0) * HID + k0 + seg * 8;
#pragma unroll
    for (int i = 0; i < 4; i++) {
        const uint32_t off = (uint32_t)(r0 + i * 32) * ROWB + seg * 16;
        cp_async16(base + off, ga + (size_t)i * 32 * HID);
    }
#pragma unroll
    for (int i = 0; i < 8; i++) {
        const uint32_t off = (uint32_t)(r0 + i * 32) * ROWB + seg * 16;
        cp_async16(base + A_ST + off, gb + (size_t)i * 32 * HID);
    }
}

__global__ __launch_bounds__(256, 1)
void mma_gemm_kernel(const __half* __restrict__ x,
                     const __half* __restrict__ w,
                     const float* __restrict__ lB,
                     float* __restrict__ out) {
    extern __shared__ __align__(16) char dsm[];
    const uint32_t tiles = smem_u32(dsm);

    __shared__ __align__(8) unsigned long long s_bar[2 * STAGES];
    const uint32_t bfull  = smem_u32(s_bar);
    const uint32_t bempty = bfull + 8 * STAGES;

    const int tid  = threadIdx.x;
    const int wid  = tid >> 5;
    const int lane = tid & 31;
    const int wm   = (wid & 1) * 64;
    const int wn   = (wid >> 1) * 64;
    const int m0   = blockIdx.y * BM;
    const int n0   = blockIdx.x * BN;

    uint32_t aoff[4];
#pragma unroll
    for (int mt = 0; mt < 4; mt++)
        aoff[mt] = (uint32_t)(wm + mt * 16 + (lane & 15)) * ROWB + (lane >> 4) * 16;
    uint32_t boff[8];
#pragma unroll
    for (int nt = 0; nt < 8; nt++)
        boff[nt] = (uint32_t)(A_ST + (wn + nt * 8 + (lane & 7)) * ROWB) + (lane >> 3) * 16;

    float c[4][8][4];
#pragma unroll
    for (int i = 0; i < 4; i++)
#pragma unroll
        for (int j = 0; j < 8; j++)
#pragma unroll
            for (int t = 0; t < 4; t++) c[i][j][t] = 0.f;

    if (tid == 0) {
#pragma unroll
        for (int s = 0; s < STAGES; s++) {
            MBAR_INIT(bfull  + 8 * s, 256);
            MBAR_INIT(bempty + 8 * s, 256);
        }
    }
    __syncthreads();

    load_chunk(tiles + 0 * STAGE_BYTES, x, w, m0, n0, 0 * BK, tid);
    CPA_MBAR_ARRIVE(bfull + 0);
    load_chunk(tiles + 1 * STAGE_BYTES, x, w, m0, n0, 1 * BK, tid);
    CPA_MBAR_ARRIVE(bfull + 8);

    uint32_t Bf[8][4], A0[4][4], A1[4][4];

#define SLOT(S, S2, PF, PE, DOWAIT, KK)                                        \
    if ((KK) < NCHUNK) {                                                       \
        mbar_wait(bfull + 8 * (S), (PF));                                      \
        const uint32_t sbase = tiles + (S) * STAGE_BYTES;                      \
        _Pragma("unroll")                                                      \
        for (int nt = 0; nt < 8; nt++) ldsm4(Bf[nt], sbase + boff[nt]);        \
        _Pragma("unroll")                                                      \
        for (int mt = 0; mt < 4; mt++) ldsm4(A0[mt], sbase + aoff[mt]);        \
        _Pragma("unroll")                                                      \
        for (int mt = 0; mt < 4; mt++) ldsm4(A1[mt], sbase + aoff[mt] + 32);   \
        _Pragma("unroll")                                                      \
        for (int mt = 0; mt < 4; mt++)                                         \
            _Pragma("unroll")                                                  \
            for (int nt = 0; nt < 8; nt++)                                     \
                mma_f16(c[mt][nt], A0[mt], Bf[nt][0], Bf[nt][1]);              \
        if ((KK) + 2 < NCHUNK) {                                               \
            if (DOWAIT) mbar_wait(bempty + 8 * (S2), (PE));                    \
            load_chunk(tiles + (S2) * STAGE_BYTES, x, w, m0, n0,               \
                       ((KK) + 2) * BK, tid);                                  \
            CPA_MBAR_ARRIVE(bfull + 8 * (S2));                                 \
        }                                                                      \
        _Pragma("unroll")                                                      \
        for (int mt = 0; mt < 4; mt++) ldsm4(A0[mt], sbase + aoff[mt] + 64);   \
        _Pragma("unroll")                                                      \
        for (int mt = 0; mt < 4; mt++)                                         \
            _Pragma("unroll")                                                  \
            for (int nt = 0; nt < 8; nt++)                                     \
                mma_f16(c[mt][nt], A1[mt], Bf[nt][2], Bf[nt][3]);              \
        _Pragma("unroll")                                                      \
        for (int nt = 0; nt < 8; nt++) ldsm4(Bf[nt], sbase + boff[nt] + 64);   \
        _Pragma("unroll")                                                      \
        for (int mt = 0; mt < 4; mt++) ldsm4(A1[mt], sbase + aoff[mt] + 96);   \
        _Pragma("unroll")                                                      \
        for (int mt = 0; mt < 4; mt++)                                         \
            _Pragma("unroll")                                                  \
            for (int nt = 0; nt < 8; nt++)                                     \
                mma_f16(c[mt][nt], A0[mt], Bf[nt][0], Bf[nt][1]);              \
        MBAR_ARRIVE(bempty + 8 * (S));                                         \
        _Pragma("unroll")                                                      \
        for (int mt = 0; mt < 4; mt++)                                         \
            _Pragma("unroll")                                                  \
            for (int nt = 0; nt < 8; nt++)                                     \
                mma_f16(c[mt][nt], A1[mt], Bf[nt][2], Bf[nt][3]);              \
    }

    for (int j = 0; j < NROUND; j++) {
        const uint32_t pf = (uint32_t)(j & 1);
        const uint32_t pm = (uint32_t)((j - 1) & 1);
        SLOT(0, 2, pf, pm, (j >= 1), 3 * j + 0);
        SLOT(1, 0, pf, pf, true,     3 * j + 1);
        SLOT(2, 1, pf, pf, true,     3 * j + 2);
    }
#undef SLOT

    // ---- epilogue: add LoRA delta, write out ----
    const int rowg = lane >> 2;
    const int colg = (lane & 3) * 2;
#pragma unroll
    for (int mt = 0; mt < 4; mt++) {
#pragma unroll
        for (int hr = 0; hr < 2; hr++) {
            const int row = m0 + wm + mt * 16 + hr * 8 + rowg;
            const int e   = g_top1[row];
            const float4* zz = reinterpret_cast<const float4*>(g_zs + (size_t)row * RNK);
            const float4 z0 = zz[0], z1 = zz[1];
            const float* lbe = lB + (size_t)e * HID * RNK;
            float* orow = out + (size_t)row * HID;
#pragma unroll
            for (int nt = 0; nt < 8; nt++) {
                const int col = n0 + wn + nt * 8 + colg;
                const float4* bp =
                    reinterpret_cast<const float4*>(lbe + (size_t)col * RNK);
                const float4 b0 = bp[0], b1 = bp[1];
                const float4* bq =
                    reinterpret_cast<const float4*>(lbe + (size_t)(col + 1) * RNK);
                const float4 q0 = bq[0], q1 = bq[1];
                float d0 = z0.x * b0.x + z0.y * b0.y + z0.z * b0.z + z0.w * b0.w
                         + z1.x * b1.x + z1.y * b1.y + z1.z * b1.z + z1.w * b1.w;
                float d1 = z0.x * q0.x + z0.y * q0.y + z0.z * q0.z + z0.w * q0.w
                         + z1.x * q1.x + z1.y * q1.y + z1.z * q1.z + z1.w * q1.w;
                float2 res = make_float2(c[mt][nt][hr * 2 + 0] + d0,
                                         c[mt][nt][hr * 2 + 1] + d1);
                *reinterpret_cast<float2*>(orow + col) = res;
            }
        }
    }
}

// ---------------------------------------------------------------------------
extern "C" void kernel_launch(void* const* d_in, const int* in_sizes, int n_in,
                              void* d_out, int out_size) {
    const float* x    = (const float*)d_in[0];
    const float* W_up = (const float*)d_in[1];
    const float* gw   = (const float*)d_in[2];
    const float* bias = (const float*)d_in[3];
    const float* lA   = (const float*)d_in[4];
    const float* lBm  = (const float*)d_in[5];
    float* out        = (float*)d_out;

    const int N = in_sizes[0] / HID;   // 16384 tokens

    static cudaStream_t s2 = nullptr;
    static cudaEvent_t  evFork = nullptr, evJoin = nullptr;
    if (s2 == nullptr) {
        cudaStreamCreateWithFlags(&s2, cudaStreamNonBlocking);
        cudaEventCreateWithFlags(&evFork, cudaEventDisableTiming);
        cudaEventCreateWithFlags(&evJoin, cudaEventDisableTiming);
        cudaFuncSetAttribute(mma_gemm_kernel,
                             cudaFuncAttributeMaxDynamicSharedMemorySize, DYN_SMEM);
        cudaFuncSetAttribute(mma_gemm_kernel,
                             cudaFuncAttributePreferredSharedMemoryCarveout, 100);
        cudaFuncSetAttribute(zgemm_kernel,
                             cudaFuncAttributeMaxDynamicSharedMemorySize, ZSMEM);
    }

    __half* xh  = nullptr;
    __half* wh  = nullptr;
    __half* lah = nullptr;
    cudaGetSymbolAddress((void**)&xh,  g_xh);
    cudaGetSymbolAddress((void**)&wh,  g_wh);
    cudaGetSymbolAddress((void**)&lah, g_lAh);

    // fork: W + lA conversion on s2, gate on main
    cudaEventRecord(evFork, 0);
    cudaStreamWaitEvent(s2, evFork, 0);
    cvt_f16_kernel<<<2048, 256, 0, s2>>>((const float4*)W_up, (uint4*)wh,
                                         HID * HID / 8);
    cvt_f16_kernel<<<64, 256, 0, s2>>>((const float4*)lA, (uint4*)lah,
                                       ZCOLS * HID / 8);
    cudaEventRecord(evJoin, s2);

    gate_light_kernel<<<N, 128>>>(x, gw, bias);

    cudaStreamWaitEvent(0, evJoin, 0);   // zgemm needs g_lAh; mma needs g_wh

    zgemm_kernel<<<N / BM, 256, ZSMEM>>>(xh);

    dim3 grid(HID / BN, N / BM);       // (16, 128)
    mma_gemm_kernel<<<grid, 256, DYN_SMEM>>>(xh, wh, lBm, out);
}